// round 10
// baseline (speedup 1.0000x reference)
#include <cuda_runtime.h>
#include <cstdint>
#include <math.h>

#define S_T   12
#define NN    16384
#define EE    262144          // 2^18
#define D     128
#define BB    64
#define TT    3072            // S*N/B
#define ROWS  (S_T*NN)        // 196608
#define NEDGE (S_T*EE)        // 3,145,728
#define NRB   1536            // row-blocks of 128 rows (= 2 timesteps each)
#define TSPLIT 1024           // LSTM split point (timesteps)
#define ITEM_OFS 2048         // first gatesx item handled inside combo (= rb 512)
#define NITEMS_TOT (NRB*4)    // 6144

// ---- scratch (static device allocations; no runtime alloc allowed) ----
__device__ __align__(16) float g_support[(size_t)ROWS * D];     // ~100 MB
__device__ __align__(16) float g_acc[(size_t)ROWS * D];         // ~100 MB
__device__ __align__(16) float g_gx[(size_t)ROWS * 512];        // ~402 MB
__device__ int g_deg[ROWS];
__device__ int g_off[ROWS];
__device__ int g_cur[ROWS];
__device__ int g_bsum[256];
__device__ __align__(16) int2 g_epack[NEDGE];                   // (src, val_bits), CSR order
__device__ int g_ticket;
__device__ __align__(16) float g_hstate[BB * 128];
__device__ __align__(16) float g_cstate[BB * 128];

// ---- packed f32x2 helpers ----
typedef unsigned long long u64;
__device__ __forceinline__ void ffma2(u64& d, u64 a, u64 b, u64 c) {
    asm("fma.rn.f32x2 %0, %1, %2, %3;" : "=l"(d) : "l"(a), "l"(b), "l"(c));
}
__device__ __forceinline__ u64 bcast2(float x) {
    u64 r;
    asm("mov.b64 %0, {%1, %1};" : "=l"(r) : "f"(x));
    return r;
}
__device__ __forceinline__ float2 unpack2(u64 v) {
    float2 r;
    asm("mov.b64 {%0, %1}, %2;" : "=f"(r.x), "=f"(r.y) : "l"(v));
    return r;
}
__device__ __forceinline__ float fsigm(float x) {
    return __fdividef(1.f, 1.f + __expf(-x));
}
__device__ __forceinline__ float ftanh(float x) {
    return __fdividef(2.f, 1.f + __expf(-2.f * x)) - 1.f;
}

// ============================================================
// init: zero degree counters + ticket
// ============================================================
__global__ void init_kernel() {
    int gid = blockIdx.x * 1024 + threadIdx.x;
    g_deg[gid] = 0;
    if (gid == 0) g_ticket = 0;
}

// ============================================================
// support tile (device fn): 128x128 of support = xs @ W
// ============================================================
__device__ __forceinline__ void support_tile(int blk, const float* __restrict__ X,
                                             const float* __restrict__ W) {
    extern __shared__ float sm[];
    float* As = sm;                 // [64][132]  (As[k][r])
    float* Bs = sm + 64 * 132;      // [64][132]  (Bs[k][c])

    int tid = threadIdx.x;
    int tx = tid & 15, ty = tid >> 4;
    size_t rowbase = (size_t)blk * 128;

    u64 accp[8][4];
#pragma unroll
    for (int i = 0; i < 8; ++i)
#pragma unroll
        for (int jj = 0; jj < 4; ++jj) accp[i][jj] = 0ull;

    for (int k0 = 0; k0 < 128; k0 += 64) {
        __syncthreads();
        for (int idx = tid; idx < 128 * 64; idx += 256) {
            int r = idx >> 6, k = idx & 63;
            As[k * 132 + r] = X[(rowbase + r) * 128 + k0 + k];
        }
        for (int idx = tid; idx < 64 * 128; idx += 256) {
            int k = idx >> 7, c = idx & 127;
            Bs[k * 132 + c] = W[(size_t)(k0 + k) * 128 + c];
        }
        __syncthreads();
#pragma unroll
        for (int k = 0; k < 64; ++k) {
            ulonglong2 b0 = *(const ulonglong2*)&Bs[k * 132 + tx * 4];
            ulonglong2 b1 = *(const ulonglong2*)&Bs[k * 132 + 64 + tx * 4];
            float4 a0 = *(const float4*)&As[k * 132 + ty * 4];
            float4 a1 = *(const float4*)&As[k * 132 + 64 + ty * 4];
            float af[8] = {a0.x,a0.y,a0.z,a0.w,a1.x,a1.y,a1.z,a1.w};
#pragma unroll
            for (int i = 0; i < 8; ++i) {
                u64 ap = bcast2(af[i]);
                ffma2(accp[i][0], ap, b0.x, accp[i][0]);
                ffma2(accp[i][1], ap, b0.y, accp[i][1]);
                ffma2(accp[i][2], ap, b1.x, accp[i][2]);
                ffma2(accp[i][3], ap, b1.y, accp[i][3]);
            }
        }
    }
#pragma unroll
    for (int i = 0; i < 8; ++i) {
        int r = (i < 4) ? (ty * 4 + i) : (64 + ty * 4 + i - 4);
        float* crow = g_support + (rowbase + r) * 128;
        float2 v0 = unpack2(accp[i][0]), v1 = unpack2(accp[i][1]);
        float2 v2 = unpack2(accp[i][2]), v3 = unpack2(accp[i][3]);
        *(float4*)&crow[tx * 4]      = make_float4(v0.x, v0.y, v1.x, v1.y);
        *(float4*)&crow[64 + tx * 4] = make_float4(v2.x, v2.y, v3.x, v3.y);
    }
}

// ============================================================
// gatesx tile (device fn): rows [rb*128, rb*128+128), cols cb*128
// ============================================================
__device__ __forceinline__ void gatesx_tile(int rb, int cb,
                                            const float* __restrict__ wih,
                                            const float* __restrict__ gcn_bias) {
    extern __shared__ float sm[];
    float* As = sm;                 // [64][132]  As[k][r] = relu(acc+b)
    float* Bs = sm + 64 * 132;      // [64][132]  Bs[k][c] = wih[cb*128+c][k]

    int tid = threadIdx.x;
    int tx = tid & 15, ty = tid >> 4;
    size_t rowbase = (size_t)rb * 128;

    u64 accp[8][4];
#pragma unroll
    for (int i = 0; i < 8; ++i)
#pragma unroll
        for (int jj = 0; jj < 4; ++jj) accp[i][jj] = 0ull;

    for (int k0 = 0; k0 < 128; k0 += 64) {
        __syncthreads();
        for (int idx = tid; idx < 128 * 64; idx += 256) {
            int r = idx >> 6, k = idx & 63;
            float x = g_acc[(rowbase + r) * 128 + k0 + k] + __ldg(&gcn_bias[k0 + k]);
            As[k * 132 + r] = fmaxf(x, 0.f);
        }
        for (int idx = tid; idx < 128 * 64; idx += 256) {     // idx = c*64 + k
            int c = idx >> 6, k = idx & 63;
            Bs[k * 132 + c] = wih[((size_t)(cb * 128 + c)) * 128 + k0 + k];
        }
        __syncthreads();
#pragma unroll
        for (int k = 0; k < 64; ++k) {
            ulonglong2 b0 = *(const ulonglong2*)&Bs[k * 132 + tx * 4];
            ulonglong2 b1 = *(const ulonglong2*)&Bs[k * 132 + 64 + tx * 4];
            float4 a0 = *(const float4*)&As[k * 132 + ty * 4];
            float4 a1 = *(const float4*)&As[k * 132 + 64 + ty * 4];
            float af[8] = {a0.x,a0.y,a0.z,a0.w,a1.x,a1.y,a1.z,a1.w};
#pragma unroll
            for (int i = 0; i < 8; ++i) {
                u64 ap = bcast2(af[i]);
                ffma2(accp[i][0], ap, b0.x, accp[i][0]);
                ffma2(accp[i][1], ap, b0.y, accp[i][1]);
                ffma2(accp[i][2], ap, b1.x, accp[i][2]);
                ffma2(accp[i][3], ap, b1.y, accp[i][3]);
            }
        }
    }
#pragma unroll
    for (int i = 0; i < 8; ++i) {
        int r = (i < 4) ? (ty * 4 + i) : (64 + ty * 4 + i - 4);
        float* crow = g_gx + (rowbase + r) * 512 + cb * 128;
        float2 v0 = unpack2(accp[i][0]), v1 = unpack2(accp[i][1]);
        float2 v2 = unpack2(accp[i][2]), v3 = unpack2(accp[i][3]);
        *(float4*)&crow[tx * 4]      = make_float4(v0.x, v0.y, v1.x, v1.y);
        *(float4*)&crow[64 + tx * 4] = make_float4(v2.x, v2.y, v3.x, v3.y);
    }
}

// ============================================================
// gather rows [blk*8, blk*8+8) (device fn, warp per row)
// ============================================================
__device__ __forceinline__ void gather_rows(int blk) {
    int wid  = blk * 8 + (threadIdx.x >> 5);          // row id
    int lane = threadIdx.x & 31;
    int s = wid >> 14;                                // NN = 2^14

    int start = g_off[wid];
    int cnt   = g_deg[wid];

    const int2*  epk  = g_epack + start;
    const float* supp = g_support + (size_t)s * NN * D + lane * 4;

    float ax = 0.f, ay = 0.f, az = 0.f, aw = 0.f;
    int i = 0;
    for (; i + 4 <= cnt; i += 4) {
        int2 p0 = __ldg(&epk[i + 0]);
        int2 p1 = __ldg(&epk[i + 1]);
        int2 p2 = __ldg(&epk[i + 2]);
        int2 p3 = __ldg(&epk[i + 3]);
        float4 m0 = *(const float4*)(supp + (size_t)p0.x * D);
        float4 m1 = *(const float4*)(supp + (size_t)p1.x * D);
        float4 m2 = *(const float4*)(supp + (size_t)p2.x * D);
        float4 m3 = *(const float4*)(supp + (size_t)p3.x * D);
        float v0 = __int_as_float(p0.y), v1 = __int_as_float(p1.y);
        float v2 = __int_as_float(p2.y), v3 = __int_as_float(p3.y);
        ax += v0 * m0.x; ay += v0 * m0.y; az += v0 * m0.z; aw += v0 * m0.w;
        ax += v1 * m1.x; ay += v1 * m1.y; az += v1 * m1.z; aw += v1 * m1.w;
        ax += v2 * m2.x; ay += v2 * m2.y; az += v2 * m2.z; aw += v2 * m2.w;
        ax += v3 * m3.x; ay += v3 * m3.y; az += v3 * m3.z; aw += v3 * m3.w;
    }
    for (; i < cnt; ++i) {
        int2 p = __ldg(&epk[i]);
        float v = __int_as_float(p.y);
        float4 m = *(const float4*)(supp + (size_t)p.x * D);
        ax += v * m.x; ay += v * m.y; az += v * m.z; aw += v * m.w;
    }
    *(float4*)(g_acc + (size_t)wid * D + lane * 4) = make_float4(ax, ay, az, aw);
}

// ============================================================
// K_a: support tiles (blocks 0..1535) || histogram (rest)
// ============================================================
__global__ void __launch_bounds__(256)
ka_kernel(const float* __restrict__ X, const float* __restrict__ W,
          const int* __restrict__ adj_idx) {
    if (blockIdx.x < 1536) { support_tile(blockIdx.x, X, W); return; }
    int gid = (blockIdx.x - 1536) * 256 + threadIdx.x;    // 0..NEDGE-1
    int s = gid >> 18, e = gid & (EE - 1);
    int dst = adj_idx[(size_t)s * 2 * EE + e];
    atomicAdd(&g_deg[s * NN + dst], 1);
}

// ============================================================
// CSR scans + fill
// ============================================================
__global__ void scan1_kernel() {                 // 192 blocks x 1024
    __shared__ int tmp[1024];
    int tid = threadIdx.x;
    int gid = blockIdx.x * 1024 + tid;
    int x = g_deg[gid];
    tmp[tid] = x;
    __syncthreads();
#pragma unroll
    for (int d = 1; d < 1024; d <<= 1) {
        int t = (tid >= d) ? tmp[tid - d] : 0;
        __syncthreads();
        tmp[tid] += t;
        __syncthreads();
    }
    g_off[gid] = tmp[tid] - x;                   // exclusive
    if (tid == 1023) g_bsum[blockIdx.x] = tmp[tid];
}

__global__ void scan2_kernel() {                 // 1 block x 256
    __shared__ int tmp[256];
    int tid = threadIdx.x;
    int x = (tid < 192) ? g_bsum[tid] : 0;
    tmp[tid] = x;
    __syncthreads();
#pragma unroll
    for (int d = 1; d < 256; d <<= 1) {
        int t = (tid >= d) ? tmp[tid - d] : 0;
        __syncthreads();
        tmp[tid] += t;
        __syncthreads();
    }
    if (tid < 192) g_bsum[tid] = tmp[tid] - x;   // exclusive
}

__global__ void scan3_kernel() {                 // 192 blocks x 1024
    int gid = blockIdx.x * 1024 + threadIdx.x;
    int v = g_off[gid] + g_bsum[blockIdx.x];
    g_off[gid] = v;
    g_cur[gid] = v;
}

__global__ void fill_kernel(const int* __restrict__ adj_idx,
                            const float* __restrict__ adj_val) {
    int gid = blockIdx.x * 1024 + threadIdx.x;
    int s = gid >> 18, e = gid & (EE - 1);
    const int* ib = adj_idx + (size_t)s * 2 * EE;
    int dst = ib[e];
    int src = ib[EE + e];
    float v  = adj_val[(size_t)s * EE + e];
    int pos = atomicAdd(&g_cur[s * NN + dst], 1);
    g_epack[pos] = make_int2(src, __float_as_int(v));
}

// ============================================================
// gatherA: rows for s<4 (blocks 0..8191)
// ============================================================
__global__ void __launch_bounds__(256)
gatherA_kernel() { gather_rows(blockIdx.x); }

// ============================================================
// K_b: gatesxA tiles rb<512 (blocks 0..2047) || gather s>=4
// ============================================================
__global__ void __launch_bounds__(256)
kb_kernel(const float* __restrict__ wih, const float* __restrict__ gb) {
    if (blockIdx.x < 2048) { gatesx_tile(blockIdx.x >> 2, blockIdx.x & 3, wih, gb); return; }
    gather_rows(blockIdx.x - 2048 + 8192);
}

// ============================================================
// LSTM chain over [t0, t1): one CTA per batch lane, 512 thr,
// K-split-2: thread (jj, half) computes outputs {jj, jj+256}
// over k in [64*half, 64*half+64). 16 smem + 48 reg weights
// per (output, half). h-broadcast wavefronts halved.
// ============================================================
__device__ __forceinline__ void lstm_chain(
    int b, int t0, int t1,
    const float* __restrict__ hin, const float* __restrict__ cin,
    const float* __restrict__ whh, const float* __restrict__ bih,
    const float* __restrict__ bhh, float* __restrict__ out)
{
    extern __shared__ float sm[];
    float* sWs = sm;                  // [1024 slices][16] stride 20
    float* sH  = sm + 1024 * 20;      // [128]
    float* sC  = sH + 128;            // [128]
    float* sG  = sC + 128;            // [512]
    float* sP0 = sG + 512;            // [256] half1's partial of output jj
    float* sP1 = sP0 + 256;           // [256] half0's partial of output jj+256

    int j = threadIdx.x;              // 0..511  (finalizes output j)
    int jj = j & 255, half = j >> 8;
    int o0 = jj, o1 = jj + 256;
    int kbase = half * 64;

    // smem weights: slice = (o<<1)|h holds whh[o][64h .. 64h+16)
    for (int idx = j; idx < 1024 * 16; idx += 512) {
        int slice = idx >> 4, kk = idx & 15;
        int o = slice >> 1, hh = slice & 1;
        sWs[slice * 20 + kk] = whh[(size_t)o * 128 + hh * 64 + kk];
    }
    // reg weights: k in [kbase+16, kbase+64) for both outputs
    u64 wr0[24], wr1[24];
#pragma unroll
    for (int m = 0; m < 24; ++m) {
        wr0[m] = *(const u64*)&whh[(size_t)o0 * 128 + kbase + 16 + 2 * m];
        wr1[m] = *(const u64*)&whh[(size_t)o1 * 128 + kbase + 16 + 2 * m];
    }

    if (j < 128) {
        sH[j] = hin[b * 128 + j];
        sC[j] = cin[b * 128 + j];
    }
    float bias = bih[j] + bhh[j];
    const float* gxp = g_gx + (size_t)b * 512 + j;
    float gx_cur = gxp[(size_t)t0 * 32768];
    __syncthreads();

    const float* w0p = &sWs[((o0 << 1) | half) * 20];
    const float* w1p = &sWs[((o1 << 1) | half) * 20];

    for (int t = t0; t < t1; ++t) {
        float gx_next = (t + 1 < t1) ? gxp[(size_t)(t + 1) * 32768] : 0.f;

        u64 a0 = 0ull, c0_ = 0ull, a1 = 0ull, c1_ = 0ull;
#pragma unroll
        for (int kk = 0; kk < 16; kk += 4) {
            ulonglong2 hv = *(const ulonglong2*)&sH[kbase + kk];
            ulonglong2 w0 = *(const ulonglong2*)&w0p[kk];
            ulonglong2 w1 = *(const ulonglong2*)&w1p[kk];
            ffma2(a0, hv.x, w0.x, a0);  ffma2(c0_, hv.y, w0.y, c0_);
            ffma2(a1, hv.x, w1.x, a1);  ffma2(c1_, hv.y, w1.y, c1_);
        }
#pragma unroll
        for (int kk = 0; kk < 48; kk += 4) {
            ulonglong2 hv = *(const ulonglong2*)&sH[kbase + 16 + kk];
            ffma2(a0, hv.x, wr0[kk / 2], a0);      ffma2(c0_, hv.y, wr0[kk / 2 + 1], c0_);
            ffma2(a1, hv.x, wr1[kk / 2], a1);      ffma2(c1_, hv.y, wr1[kk / 2 + 1], c1_);
        }
        float2 q0 = unpack2(a0), q1 = unpack2(c0_);
        float p0 = (q0.x + q0.y) + (q1.x + q1.y);      // partial of o0, this half
        float2 q2 = unpack2(a1), q3 = unpack2(c1_);
        float p1 = (q2.x + q2.y) + (q3.x + q3.y);      // partial of o1, this half

        if (half) sP0[jj] = p0; else sP1[jj] = p1;     // partner's missing half
        __syncthreads();

        float own   = half ? p1 : p0;
        float other = half ? sP1[jj] : sP0[jj];
        float pre = own + other + gx_cur + bias;
        int gate = j >> 7;                             // 0:i 1:f 2:g 3:o
        sG[j] = (gate == 2) ? ftanh(pre) : fsigm(pre);
        __syncthreads();

        if (j < 128) {
            float c = sG[128 + j] * sC[j] + sG[j] * sG[256 + j];
            sC[j] = c;
            float hval = sG[384 + j] * ftanh(c);
            sH[j] = hval;
            out[((size_t)t * 64 + b) * 128 + j] = hval;
        }
        __syncthreads();
        gx_cur = gx_next;
    }

    if (j < 128) {
        g_hstate[b * 128 + j] = sH[j];
        g_cstate[b * 128 + j] = sC[j];
    }
}

// ============================================================
// COMBO kernel: 148 CTAs x 512 threads, NO cross-CTA comms.
//  CTA 0..63   : LSTM for t in [0, TSPLIT)
//  CTA 64..147 : gates_x producer for items [ITEM_OFS, NITEMS_TOT)
// ============================================================
__global__ void __launch_bounds__(512, 1)
combo_kernel(const float* __restrict__ wih,  const float* __restrict__ gb,
             const float* __restrict__ whh,
             const float* __restrict__ bih,  const float* __restrict__ bhh,
             const float* __restrict__ h0,   const float* __restrict__ c0,
             float* __restrict__ out) {
    if (blockIdx.x < 64) {
        lstm_chain(blockIdx.x, 0, TSPLIT, h0, c0, whh, bih, bhh, out);
        return;
    }

    // ---------- producer: gates_x for rb >= 512 ----------
    extern __shared__ float sm[];
    float* As = sm;                 // [64][132]
    float* Bs = sm + 64 * 132;      // [64][132]
    __shared__ int sItem;
    int tid = threadIdx.x;
    int tx = tid & 15, ty = tid >> 4;       // ty 0..31 -> 4 rows each

    for (;;) {
        if (tid == 0) sItem = ITEM_OFS + atomicAdd(&g_ticket, 1);
        __syncthreads();
        int item = sItem;
        if (item >= NITEMS_TOT) break;
        int rb = item >> 2, cb = item & 3;
        size_t rowbase = (size_t)rb * 128;

        u64 accp[4][4];
#pragma unroll
        for (int i = 0; i < 4; ++i)
#pragma unroll
            for (int jj = 0; jj < 4; ++jj) accp[i][jj] = 0ull;

        for (int k0 = 0; k0 < 128; k0 += 64) {
            __syncthreads();
            for (int idx = tid; idx < 128 * 64; idx += 512) {
                int r = idx >> 6, k = idx & 63;
                float x = g_acc[(rowbase + r) * 128 + k0 + k] + __ldg(&gb[k0 + k]);
                As[k * 132 + r] = fmaxf(x, 0.f);
            }
            for (int idx = tid; idx < 128 * 64; idx += 512) {
                int c = idx >> 6, k = idx & 63;
                Bs[k * 132 + c] = wih[((size_t)(cb * 128 + c)) * 128 + k0 + k];
            }
            __syncthreads();
#pragma unroll
            for (int k = 0; k < 64; ++k) {
                ulonglong2 b0 = *(const ulonglong2*)&Bs[k * 132 + tx * 4];
                ulonglong2 b1 = *(const ulonglong2*)&Bs[k * 132 + 64 + tx * 4];
                float4 a = *(const float4*)&As[k * 132 + ty * 4];
                float af[4] = {a.x, a.y, a.z, a.w};
#pragma unroll
                for (int i = 0; i < 4; ++i) {
                    u64 ap = bcast2(af[i]);
                    ffma2(accp[i][0], ap, b0.x, accp[i][0]);
                    ffma2(accp[i][1], ap, b0.y, accp[i][1]);
                    ffma2(accp[i][2], ap, b1.x, accp[i][2]);
                    ffma2(accp[i][3], ap, b1.y, accp[i][3]);
                }
            }
        }
#pragma unroll
        for (int i = 0; i < 4; ++i) {
            float* crow = g_gx + (rowbase + ty * 4 + i) * 512 + cb * 128;
            float2 v0 = unpack2(accp[i][0]), v1 = unpack2(accp[i][1]);
            float2 v2 = unpack2(accp[i][2]), v3 = unpack2(accp[i][3]);
            *(float4*)&crow[tx * 4]      = make_float4(v0.x, v0.y, v1.x, v1.y);
            *(float4*)&crow[64 + tx * 4] = make_float4(v2.x, v2.y, v3.x, v3.y);
        }
        // consumers of these gx rows run in a LATER kernel launch
    }
}

// ============================================================
// LSTM part B: t in [TSPLIT, TT), state from device globals
// ============================================================
__global__ void __launch_bounds__(512, 1)
lstm2_kernel(const float* __restrict__ whh,
             const float* __restrict__ bih, const float* __restrict__ bhh,
             float* __restrict__ out) {
    lstm_chain(blockIdx.x, TSPLIT, TT, g_hstate, g_cstate, whh, bih, bhh, out);
}

// ============================================================
// launch
// ============================================================
extern "C" void kernel_launch(void* const* d_in, const int* in_sizes, int n_in,
                              void* d_out, int out_size) {
    const int*   adj_idx = (const int*)  d_in[0];
    const float* adj_val = (const float*)d_in[1];
    const float* xs      = (const float*)d_in[2];
    const float* gw      = (const float*)d_in[3];
    const float* gb      = (const float*)d_in[4];
    const float* wih     = (const float*)d_in[5];
    const float* whh     = (const float*)d_in[6];
    const float* bih     = (const float*)d_in[7];
    const float* bhh     = (const float*)d_in[8];
    const float* h0      = (const float*)d_in[9];
    const float* c0      = (const float*)d_in[10];
    float* out = (float*)d_out;

    (void)in_sizes; (void)n_in; (void)out_size;

    const int GEMM_SMEM = 2 * 64 * 132 * 4;                               // 67584
    const int LSTM_SMEM = (1024 * 20 + 128 + 128 + 512 + 256 + 256) * 4;  // 87040

    static bool attr_done = false;
    if (!attr_done) {
        cudaFuncSetAttribute(ka_kernel,     cudaFuncAttributeMaxDynamicSharedMemorySize, GEMM_SMEM);
        cudaFuncSetAttribute(kb_kernel,     cudaFuncAttributeMaxDynamicSharedMemorySize, GEMM_SMEM);
        cudaFuncSetAttribute(combo_kernel,  cudaFuncAttributeMaxDynamicSharedMemorySize, LSTM_SMEM);
        cudaFuncSetAttribute(lstm2_kernel,  cudaFuncAttributeMaxDynamicSharedMemorySize, LSTM_SMEM);
        attr_done = true;
    }

    // init
    init_kernel<<<192, 1024>>>();

    // K_a: support tiles (1536) || histogram (12288)
    ka_kernel<<<1536 + NEDGE / 256, 256, GEMM_SMEM>>>(xs, gw, adj_idx);

    // scans + fill
    scan1_kernel<<<192, 1024>>>();
    scan2_kernel<<<1, 256>>>();
    scan3_kernel<<<192, 1024>>>();
    fill_kernel<<<NEDGE / 1024, 1024>>>(adj_idx, adj_val);

    // gather for s<4 (rows < 65536)
    gatherA_kernel<<<8192, 256>>>();

    // K_b: gatesxA tiles rb<512 (2048) || gather s>=4 (16384)
    kb_kernel<<<2048 + 16384, 256, GEMM_SMEM>>>(wih, gb);

    // overlap: LSTM[0,TSPLIT) on 64 CTAs || gates_x rb>=512 on 84 CTAs
    combo_kernel<<<148, 512, LSTM_SMEM>>>(wih, gb, whh, bih, bhh, h0, c0, out);

    // LSTM [TSPLIT, TT)
    lstm2_kernel<<<64, 512, LSTM_SMEM>>>(whh, bih, bhh, out);
}

// round 11
// speedup vs baseline: 1.2465x; 1.2465x over previous
#include <cuda_runtime.h>
#include <cstdint>
#include <math.h>

#define S_T   12
#define NN    16384
#define EE    262144          // 2^18
#define D     128
#define BB    64
#define TT    3072            // S*N/B
#define ROWS  (S_T*NN)        // 196608
#define NEDGE (S_T*EE)        // 3,145,728
#define NRB   1536            // row-blocks of 128 rows (= 2 timesteps each)
#define TSPLIT 1024           // LSTM split point (timesteps)
#define ITEM_OFS 2048         // first gatesx item handled inside combo (= rb 512)
#define NITEMS_TOT (NRB*4)    // 6144

// ---- scratch (static device allocations; no runtime alloc allowed) ----
__device__ __align__(16) float g_support[(size_t)ROWS * D];     // ~100 MB
__device__ __align__(16) float g_acc[(size_t)ROWS * D];         // ~100 MB
__device__ __align__(16) float g_gx[(size_t)ROWS * 512];        // ~402 MB
__device__ int g_deg[ROWS];
__device__ int g_off[ROWS];
__device__ int g_cur[ROWS];
__device__ int g_bsum[256];
__device__ __align__(16) int2 g_epack[NEDGE];                   // (src, val_bits), CSR order
__device__ int g_ticket;
__device__ __align__(16) float g_hstate[BB * 128];
__device__ __align__(16) float g_cstate[BB * 128];

// ---- packed f32x2 helpers ----
typedef unsigned long long u64;
__device__ __forceinline__ void ffma2(u64& d, u64 a, u64 b, u64 c) {
    asm("fma.rn.f32x2 %0, %1, %2, %3;" : "=l"(d) : "l"(a), "l"(b), "l"(c));
}
__device__ __forceinline__ u64 bcast2(float x) {
    u64 r;
    asm("mov.b64 %0, {%1, %1};" : "=l"(r) : "f"(x));
    return r;
}
__device__ __forceinline__ float2 unpack2(u64 v) {
    float2 r;
    asm("mov.b64 {%0, %1}, %2;" : "=f"(r.x), "=f"(r.y) : "l"(v));
    return r;
}
__device__ __forceinline__ float fsigm(float x) {
    return __fdividef(1.f, 1.f + __expf(-x));
}
__device__ __forceinline__ float ftanh(float x) {
    return __fdividef(2.f, 1.f + __expf(-2.f * x)) - 1.f;
}

// ============================================================
// init: zero degree counters + ticket
// ============================================================
__global__ void init_kernel() {
    int gid = blockIdx.x * 1024 + threadIdx.x;
    g_deg[gid] = 0;
    if (gid == 0) g_ticket = 0;
}

// ============================================================
// CSR pipeline: histogram -> scan -> fill (packs src+val)
// ============================================================
__global__ void hist_kernel(const int* __restrict__ adj_idx) {
    int gid = blockIdx.x * 1024 + threadIdx.x;   // 0..NEDGE-1
    int s = gid >> 18, e = gid & (EE - 1);
    int dst = adj_idx[(size_t)s * 2 * EE + e];
    atomicAdd(&g_deg[s * NN + dst], 1);
}

__global__ void scan1_kernel() {                 // 192 blocks x 1024
    __shared__ int tmp[1024];
    int tid = threadIdx.x;
    int gid = blockIdx.x * 1024 + tid;
    int x = g_deg[gid];
    tmp[tid] = x;
    __syncthreads();
#pragma unroll
    for (int d = 1; d < 1024; d <<= 1) {
        int t = (tid >= d) ? tmp[tid - d] : 0;
        __syncthreads();
        tmp[tid] += t;
        __syncthreads();
    }
    g_off[gid] = tmp[tid] - x;                   // exclusive
    if (tid == 1023) g_bsum[blockIdx.x] = tmp[tid];
}

__global__ void scan2_kernel() {                 // 1 block x 256
    __shared__ int tmp[256];
    int tid = threadIdx.x;
    int x = (tid < 192) ? g_bsum[tid] : 0;
    tmp[tid] = x;
    __syncthreads();
#pragma unroll
    for (int d = 1; d < 256; d <<= 1) {
        int t = (tid >= d) ? tmp[tid - d] : 0;
        __syncthreads();
        tmp[tid] += t;
        __syncthreads();
    }
    if (tid < 192) g_bsum[tid] = tmp[tid] - x;   // exclusive
}

__global__ void scan3_kernel() {                 // 192 blocks x 1024
    int gid = blockIdx.x * 1024 + threadIdx.x;
    int v = g_off[gid] + g_bsum[blockIdx.x];
    g_off[gid] = v;
    g_cur[gid] = v;
}

__global__ void fill_kernel(const int* __restrict__ adj_idx,
                            const float* __restrict__ adj_val) {
    int gid = blockIdx.x * 1024 + threadIdx.x;
    int s = gid >> 18, e = gid & (EE - 1);
    const int* ib = adj_idx + (size_t)s * 2 * EE;
    int dst = ib[e];
    int src = ib[EE + e];
    float v  = adj_val[(size_t)s * EE + e];
    int pos = atomicAdd(&g_cur[s * NN + dst], 1);
    g_epack[pos] = make_int2(src, __float_as_int(v));
}

// ============================================================
// gather: acc[row] = sum_e val[e] * support[src[e]]
// ============================================================
__global__ void __launch_bounds__(256)
gather_kernel() {
    int wid  = blockIdx.x * 8 + (threadIdx.x >> 5);   // row id
    int lane = threadIdx.x & 31;
    int s = wid >> 14;                                // NN = 2^14

    int start = g_off[wid];
    int cnt   = g_deg[wid];

    const int2*  epk  = g_epack + start;
    const float* supp = g_support + (size_t)s * NN * D + lane * 4;

    float ax = 0.f, ay = 0.f, az = 0.f, aw = 0.f;
    int i = 0;
    for (; i + 4 <= cnt; i += 4) {
        int2 p0 = __ldg(&epk[i + 0]);
        int2 p1 = __ldg(&epk[i + 1]);
        int2 p2 = __ldg(&epk[i + 2]);
        int2 p3 = __ldg(&epk[i + 3]);
        float4 m0 = *(const float4*)(supp + (size_t)p0.x * D);
        float4 m1 = *(const float4*)(supp + (size_t)p1.x * D);
        float4 m2 = *(const float4*)(supp + (size_t)p2.x * D);
        float4 m3 = *(const float4*)(supp + (size_t)p3.x * D);
        float v0 = __int_as_float(p0.y), v1 = __int_as_float(p1.y);
        float v2 = __int_as_float(p2.y), v3 = __int_as_float(p3.y);
        ax += v0 * m0.x; ay += v0 * m0.y; az += v0 * m0.z; aw += v0 * m0.w;
        ax += v1 * m1.x; ay += v1 * m1.y; az += v1 * m1.z; aw += v1 * m1.w;
        ax += v2 * m2.x; ay += v2 * m2.y; az += v2 * m2.z; aw += v2 * m2.w;
        ax += v3 * m3.x; ay += v3 * m3.y; az += v3 * m3.z; aw += v3 * m3.w;
    }
    for (; i < cnt; ++i) {
        int2 p = __ldg(&epk[i]);
        float v = __int_as_float(p.y);
        float4 m = *(const float4*)(supp + (size_t)p.x * D);
        ax += v * m.x; ay += v * m.y; az += v * m.z; aw += v * m.w;
    }
    *(float4*)(g_acc + (size_t)wid * D + lane * 4) = make_float4(ax, ay, az, aw);
}

// ============================================================
// K1: support = xs @ gcn_weight (256 threads, 8x8 reg tile)
// ============================================================
__global__ void __launch_bounds__(256)
support_kernel(const float* __restrict__ X, const float* __restrict__ W) {
    extern __shared__ float sm[];
    float* As = sm;                 // [64][132]  (As[k][r])
    float* Bs = sm + 64 * 132;      // [64][132]  (Bs[k][c])

    int tid = threadIdx.x;
    int tx = tid & 15, ty = tid >> 4;
    size_t rowbase = (size_t)blockIdx.x * 128;

    u64 accp[8][4];
#pragma unroll
    for (int i = 0; i < 8; ++i)
#pragma unroll
        for (int jj = 0; jj < 4; ++jj) accp[i][jj] = 0ull;

    for (int k0 = 0; k0 < 128; k0 += 64) {
        __syncthreads();
        for (int idx = tid; idx < 128 * 64; idx += 256) {
            int r = idx >> 6, k = idx & 63;
            As[k * 132 + r] = X[(rowbase + r) * 128 + k0 + k];
        }
        for (int idx = tid; idx < 64 * 128; idx += 256) {
            int k = idx >> 7, c = idx & 127;
            Bs[k * 132 + c] = W[(size_t)(k0 + k) * 128 + c];
        }
        __syncthreads();
#pragma unroll
        for (int k = 0; k < 64; ++k) {
            ulonglong2 b0 = *(const ulonglong2*)&Bs[k * 132 + tx * 4];
            ulonglong2 b1 = *(const ulonglong2*)&Bs[k * 132 + 64 + tx * 4];
            float4 a0 = *(const float4*)&As[k * 132 + ty * 4];
            float4 a1 = *(const float4*)&As[k * 132 + 64 + ty * 4];
            float af[8] = {a0.x,a0.y,a0.z,a0.w,a1.x,a1.y,a1.z,a1.w};
#pragma unroll
            for (int i = 0; i < 8; ++i) {
                u64 ap = bcast2(af[i]);
                ffma2(accp[i][0], ap, b0.x, accp[i][0]);
                ffma2(accp[i][1], ap, b0.y, accp[i][1]);
                ffma2(accp[i][2], ap, b1.x, accp[i][2]);
                ffma2(accp[i][3], ap, b1.y, accp[i][3]);
            }
        }
    }
#pragma unroll
    for (int i = 0; i < 8; ++i) {
        int r = (i < 4) ? (ty * 4 + i) : (64 + ty * 4 + i - 4);
        float* crow = g_support + (rowbase + r) * 128;
        float2 v0 = unpack2(accp[i][0]), v1 = unpack2(accp[i][1]);
        float2 v2 = unpack2(accp[i][2]), v3 = unpack2(accp[i][3]);
        *(float4*)&crow[tx * 4]      = make_float4(v0.x, v0.y, v1.x, v1.y);
        *(float4*)&crow[64 + tx * 4] = make_float4(v2.x, v2.y, v3.x, v3.y);
    }
}

// ============================================================
// gatesx part A: rb < TSPLIT/2 (timesteps < TSPLIT)
// grid (512, 4), 256 threads, 8x8 reg tile
// ============================================================
__global__ void __launch_bounds__(256)
gatesxA_kernel(const float* __restrict__ wih, const float* __restrict__ gcn_bias) {
    extern __shared__ float sm[];
    float* As = sm;                 // [64][132]  As[k][r] = relu(acc+b)
    float* Bs = sm + 64 * 132;      // [64][132]  Bs[k][c] = wih[cb*128+c][k]

    int tid = threadIdx.x;
    int tx = tid & 15, ty = tid >> 4;
    size_t rowbase = (size_t)blockIdx.x * 128;
    int cb = blockIdx.y;

    u64 accp[8][4];
#pragma unroll
    for (int i = 0; i < 8; ++i)
#pragma unroll
        for (int jj = 0; jj < 4; ++jj) accp[i][jj] = 0ull;

    for (int k0 = 0; k0 < 128; k0 += 64) {
        __syncthreads();
        for (int idx = tid; idx < 128 * 64; idx += 256) {
            int r = idx >> 6, k = idx & 63;
            float x = g_acc[(rowbase + r) * 128 + k0 + k] + __ldg(&gcn_bias[k0 + k]);
            As[k * 132 + r] = fmaxf(x, 0.f);
        }
        for (int idx = tid; idx < 128 * 64; idx += 256) {     // idx = c*64 + k
            int c = idx >> 6, k = idx & 63;
            Bs[k * 132 + c] = wih[((size_t)(cb * 128 + c)) * 128 + k0 + k];
        }
        __syncthreads();
#pragma unroll
        for (int k = 0; k < 64; ++k) {
            ulonglong2 b0 = *(const ulonglong2*)&Bs[k * 132 + tx * 4];
            ulonglong2 b1 = *(const ulonglong2*)&Bs[k * 132 + 64 + tx * 4];
            float4 a0 = *(const float4*)&As[k * 132 + ty * 4];
            float4 a1 = *(const float4*)&As[k * 132 + 64 + ty * 4];
            float af[8] = {a0.x,a0.y,a0.z,a0.w,a1.x,a1.y,a1.z,a1.w};
#pragma unroll
            for (int i = 0; i < 8; ++i) {
                u64 ap = bcast2(af[i]);
                ffma2(accp[i][0], ap, b0.x, accp[i][0]);
                ffma2(accp[i][1], ap, b0.y, accp[i][1]);
                ffma2(accp[i][2], ap, b1.x, accp[i][2]);
                ffma2(accp[i][3], ap, b1.y, accp[i][3]);
            }
        }
    }
#pragma unroll
    for (int i = 0; i < 8; ++i) {
        int r = (i < 4) ? (ty * 4 + i) : (64 + ty * 4 + i - 4);
        float* crow = g_gx + (rowbase + r) * 512 + cb * 128;
        float2 v0 = unpack2(accp[i][0]), v1 = unpack2(accp[i][1]);
        float2 v2 = unpack2(accp[i][2]), v3 = unpack2(accp[i][3]);
        *(float4*)&crow[tx * 4]      = make_float4(v0.x, v0.y, v1.x, v1.y);
        *(float4*)&crow[64 + tx * 4] = make_float4(v2.x, v2.y, v3.x, v3.y);
    }
}

// ============================================================
// LSTM chain over [t0, t1): one CTA per batch lane, 512 thr.
// K-split-2, conflict-free layout: thread (jj, half) computes
// partials of outputs {jj, jj+256} over k in [64*half, 64*half+64).
// Weight slice index = half*512 + o (lane stride 20 floats ->
// groups of 8 lanes cover all 32 banks: conflict-free).
// TWO barriers/step: partial exchange, then j<128 threads do
// sums + all nonlinearities + c/h update.
// ============================================================
__device__ __forceinline__ void lstm_chain(
    int b, int t0, int t1,
    const float* __restrict__ hin, const float* __restrict__ cin,
    const float* __restrict__ whh, const float* __restrict__ bih,
    const float* __restrict__ bhh, float* __restrict__ out)
{
    extern __shared__ float sm[];
    float* sWs = sm;                  // [1024 slices][16] stride 20, slice = half*512 + o
    float* sH  = sm + 1024 * 20;      // [128]
    float* sC  = sH + 128;            // [128]
    float* sP  = sC + 128;            // [1024]: sP[o*2 + half]

    int j = threadIdx.x;              // 0..511
    int jj = j & 255, half = j >> 8;  // warp-uniform half (warp = j>>5)
    int o0 = jj, o1 = jj + 256;
    int kbase = half * 64;

    // smem weights: slice (half*512 + o) holds whh[o][64*half .. 64*half+16)
    for (int idx = j; idx < 1024 * 16; idx += 512) {
        int slice = idx >> 4, kk = idx & 15;
        int hh = slice >> 9, o = slice & 511;
        sWs[slice * 20 + kk] = whh[(size_t)o * 128 + hh * 64 + kk];
    }
    // reg weights: k in [kbase+16, kbase+64) for both outputs
    u64 wr0[24], wr1[24];
#pragma unroll
    for (int m = 0; m < 24; ++m) {
        wr0[m] = *(const u64*)&whh[(size_t)o0 * 128 + kbase + 16 + 2 * m];
        wr1[m] = *(const u64*)&whh[(size_t)o1 * 128 + kbase + 16 + 2 * m];
    }

    if (j < 128) {
        sH[j] = hin[b * 128 + j];
        sC[j] = cin[b * 128 + j];
    }
    // gx + bias folded into half==0 partials
    float bias0 = bih[o0] + bhh[o0];
    float bias1 = bih[o1] + bhh[o1];
    const float* gx0p = g_gx + (size_t)b * 512 + o0;
    const float* gx1p = g_gx + (size_t)b * 512 + o1;
    float gxc0 = 0.f, gxc1 = 0.f;
    if (half == 0) {
        gxc0 = gx0p[(size_t)t0 * 32768];
        gxc1 = gx1p[(size_t)t0 * 32768];
    }
    __syncthreads();

    const float* w0p = &sWs[(half * 512 + o0) * 20];
    const float* w1p = &sWs[(half * 512 + o1) * 20];

    for (int t = t0; t < t1; ++t) {
        float gxn0 = 0.f, gxn1 = 0.f;
        if (half == 0 && t + 1 < t1) {        // warp-uniform branch
            gxn0 = gx0p[(size_t)(t + 1) * 32768];
            gxn1 = gx1p[(size_t)(t + 1) * 32768];
        }

        u64 a0 = 0ull, d0 = 0ull, a1 = 0ull, d1 = 0ull;
#pragma unroll
        for (int kk = 0; kk < 16; kk += 4) {
            ulonglong2 hv = *(const ulonglong2*)&sH[kbase + kk];
            ulonglong2 w0 = *(const ulonglong2*)&w0p[kk];
            ulonglong2 w1 = *(const ulonglong2*)&w1p[kk];
            ffma2(a0, hv.x, w0.x, a0);  ffma2(d0, hv.y, w0.y, d0);
            ffma2(a1, hv.x, w1.x, a1);  ffma2(d1, hv.y, w1.y, d1);
        }
#pragma unroll
        for (int kk = 0; kk < 48; kk += 4) {
            ulonglong2 hv = *(const ulonglong2*)&sH[kbase + 16 + kk];
            ffma2(a0, hv.x, wr0[kk / 2], a0);  ffma2(d0, hv.y, wr0[kk / 2 + 1], d0);
            ffma2(a1, hv.x, wr1[kk / 2], a1);  ffma2(d1, hv.y, wr1[kk / 2 + 1], d1);
        }
        float2 q0 = unpack2(a0), q1 = unpack2(d0);
        float2 q2 = unpack2(a1), q3 = unpack2(d1);
        float p0 = (q0.x + q0.y) + (q1.x + q1.y);
        float p1 = (q2.x + q2.y) + (q3.x + q3.y);
        if (half == 0) {                      // fold gx + bias once
            p0 += gxc0 + bias0;
            p1 += gxc1 + bias1;
        }
        sP[o0 * 2 + half] = p0;
        sP[o1 * 2 + half] = p1;
        __syncthreads();

        if (j < 128) {
            float ip = sP[j * 2]           + sP[j * 2 + 1];
            float fp = sP[(128 + j) * 2]   + sP[(128 + j) * 2 + 1];
            float gp = sP[(256 + j) * 2]   + sP[(256 + j) * 2 + 1];
            float op = sP[(384 + j) * 2]   + sP[(384 + j) * 2 + 1];
            float si = fsigm(ip), sf = fsigm(fp), so = fsigm(op), tg = ftanh(gp);
            float c = sf * sC[j] + si * tg;
            sC[j] = c;
            float hval = so * ftanh(c);
            sH[j] = hval;
            out[((size_t)t * 64 + b) * 128 + j] = hval;
        }
        __syncthreads();
        gxc0 = gxn0; gxc1 = gxn1;
    }

    if (j < 128) {
        g_hstate[b * 128 + j] = sH[j];
        g_cstate[b * 128 + j] = sC[j];
    }
}

// ============================================================
// COMBO kernel: 148 CTAs x 512 threads, NO cross-CTA comms.
//  CTA 0..63   : LSTM for t in [0, TSPLIT)
//  CTA 64..147 : gates_x producer for items [ITEM_OFS, NITEMS_TOT)
// ============================================================
__global__ void __launch_bounds__(512, 1)
combo_kernel(const float* __restrict__ wih,  const float* __restrict__ gb,
             const float* __restrict__ whh,
             const float* __restrict__ bih,  const float* __restrict__ bhh,
             const float* __restrict__ h0,   const float* __restrict__ c0,
             float* __restrict__ out) {
    if (blockIdx.x < 64) {
        lstm_chain(blockIdx.x, 0, TSPLIT, h0, c0, whh, bih, bhh, out);
        return;
    }

    // ---------- producer: gates_x for rb >= 512 ----------
    extern __shared__ float sm[];
    float* As = sm;                 // [64][132]
    float* Bs = sm + 64 * 132;      // [64][132]
    __shared__ int sItem;
    int tid = threadIdx.x;
    int tx = tid & 15, ty = tid >> 4;       // ty 0..31 -> 4 rows each

    for (;;) {
        if (tid == 0) sItem = ITEM_OFS + atomicAdd(&g_ticket, 1);
        __syncthreads();
        int item = sItem;
        if (item >= NITEMS_TOT) break;
        int rb = item >> 2, cb = item & 3;
        size_t rowbase = (size_t)rb * 128;

        u64 accp[4][4];
#pragma unroll
        for (int i = 0; i < 4; ++i)
#pragma unroll
            for (int jj = 0; jj < 4; ++jj) accp[i][jj] = 0ull;

        for (int k0 = 0; k0 < 128; k0 += 64) {
            __syncthreads();
            for (int idx = tid; idx < 128 * 64; idx += 512) {
                int r = idx >> 6, k = idx & 63;
                float x = g_acc[(rowbase + r) * 128 + k0 + k] + __ldg(&gb[k0 + k]);
                As[k * 132 + r] = fmaxf(x, 0.f);
            }
            for (int idx = tid; idx < 128 * 64; idx += 512) {
                int c = idx >> 6, k = idx & 63;
                Bs[k * 132 + c] = wih[((size_t)(cb * 128 + c)) * 128 + k0 + k];
            }
            __syncthreads();
#pragma unroll
            for (int k = 0; k < 64; ++k) {
                ulonglong2 b0 = *(const ulonglong2*)&Bs[k * 132 + tx * 4];
                ulonglong2 b1 = *(const ulonglong2*)&Bs[k * 132 + 64 + tx * 4];
                float4 a = *(const float4*)&As[k * 132 + ty * 4];
                float af[4] = {a.x, a.y, a.z, a.w};
#pragma unroll
                for (int i = 0; i < 4; ++i) {
                    u64 ap = bcast2(af[i]);
                    ffma2(accp[i][0], ap, b0.x, accp[i][0]);
                    ffma2(accp[i][1], ap, b0.y, accp[i][1]);
                    ffma2(accp[i][2], ap, b1.x, accp[i][2]);
                    ffma2(accp[i][3], ap, b1.y, accp[i][3]);
                }
            }
        }
#pragma unroll
        for (int i = 0; i < 4; ++i) {
            float* crow = g_gx + (rowbase + ty * 4 + i) * 512 + cb * 128;
            float2 v0 = unpack2(accp[i][0]), v1 = unpack2(accp[i][1]);
            float2 v2 = unpack2(accp[i][2]), v3 = unpack2(accp[i][3]);
            *(float4*)&crow[tx * 4]      = make_float4(v0.x, v0.y, v1.x, v1.y);
            *(float4*)&crow[64 + tx * 4] = make_float4(v2.x, v2.y, v3.x, v3.y);
        }
        // consumers of these gx rows run in a LATER kernel launch
    }
}

// ============================================================
// LSTM part B: t in [TSPLIT, TT), state from device globals
// ============================================================
__global__ void __launch_bounds__(512, 1)
lstm2_kernel(const float* __restrict__ whh,
             const float* __restrict__ bih, const float* __restrict__ bhh,
             float* __restrict__ out) {
    lstm_chain(blockIdx.x, TSPLIT, TT, g_hstate, g_cstate, whh, bih, bhh, out);
}

// ============================================================
// launch
// ============================================================
extern "C" void kernel_launch(void* const* d_in, const int* in_sizes, int n_in,
                              void* d_out, int out_size) {
    const int*   adj_idx = (const int*)  d_in[0];
    const float* adj_val = (const float*)d_in[1];
    const float* xs      = (const float*)d_in[2];
    const float* gw      = (const float*)d_in[3];
    const float* gb      = (const float*)d_in[4];
    const float* wih     = (const float*)d_in[5];
    const float* whh     = (const float*)d_in[6];
    const float* bih     = (const float*)d_in[7];
    const float* bhh     = (const float*)d_in[8];
    const float* h0      = (const float*)d_in[9];
    const float* c0      = (const float*)d_in[10];
    float* out = (float*)d_out;

    (void)in_sizes; (void)n_in; (void)out_size;

    const int GEMM_SMEM = 2 * 64 * 132 * 4;                       // 67584
    const int LSTM_SMEM = (1024 * 20 + 128 + 128 + 1024) * 4;     // 87040

    static bool attr_done = false;
    if (!attr_done) {
        cudaFuncSetAttribute(support_kernel, cudaFuncAttributeMaxDynamicSharedMemorySize, GEMM_SMEM);
        cudaFuncSetAttribute(gatesxA_kernel, cudaFuncAttributeMaxDynamicSharedMemorySize, GEMM_SMEM);
        cudaFuncSetAttribute(combo_kernel,   cudaFuncAttributeMaxDynamicSharedMemorySize, LSTM_SMEM);
        cudaFuncSetAttribute(lstm2_kernel,   cudaFuncAttributeMaxDynamicSharedMemorySize, LSTM_SMEM);
        attr_done = true;
    }

    // init + CSR build
    init_kernel<<<192, 1024>>>();
    hist_kernel<<<NEDGE / 1024, 1024>>>(adj_idx);
    scan1_kernel<<<192, 1024>>>();
    scan2_kernel<<<1, 256>>>();
    scan3_kernel<<<192, 1024>>>();
    fill_kernel<<<NEDGE / 1024, 1024>>>(adj_idx, adj_val);

    // support GEMM
    support_kernel<<<1536, 256, GEMM_SMEM>>>(xs, gw);

    // gather
    gather_kernel<<<ROWS / 8, 256>>>();

    // gates_x for t < TSPLIT (rb < 512)
    gatesxA_kernel<<<dim3(TSPLIT / 2, 4), 256, GEMM_SMEM>>>(wih, gb);

    // overlap: LSTM[0,TSPLIT) on 64 CTAs || gates_x rb>=512 on 84 CTAs
    combo_kernel<<<148, 512, LSTM_SMEM>>>(wih, gb, whh, bih, bhh, h0, c0, out);

    // LSTM [TSPLIT, TT)
    lstm2_kernel<<<64, 512, LSTM_SMEM>>>(whh, bih, bhh, out);
}